// round 1
// baseline (speedup 1.0000x reference)
#include <cuda_runtime.h>

#define N_X   20000
#define N_ELL 48
#define N_K   1024
#define N_TAU 600

#define N_CHUNK 4
#define T_PER_CHUNK (N_TAU / N_CHUNK)   // 150
#define K_PER_BLOCK 16
#define NG 12                            // ell groups of 4 (float4)

// Scratch partial sums: [chunk][ell][k]
__device__ float g_Tl[N_CHUNK][N_ELL][N_K];
__device__ float g_El[N_CHUNK][N_ELL][N_K];

// ---------------------------------------------------------------------------
// Kernel 1: fused interpolation + source product + tau-trapezoid partial sums.
// block: (12, 16) -> 12 ell-groups x 16 k.  grid: (64 k-blocks, 4 tau-chunks)
// ---------------------------------------------------------------------------
__global__ __launch_bounds__(192) void spectrum_k1(
    const float* __restrict__ kk_arr,
    const float* __restrict__ tau,
    const float* __restrict__ tau0p,
    const float* __restrict__ S0,
    const float* __restrict__ S1,
    const float* __restrict__ S2,
    const float* __restrict__ SE,
    const float* __restrict__ bx,
    const float* __restrict__ p0t,
    const float* __restrict__ p1t,
    const float* __restrict__ p2t,
    const float* __restrict__ pet)
{
    __shared__ float sh_d[T_PER_CHUNK];   // tau0 - tau[t]
    __shared__ float sh_w[T_PER_CHUNK];   // trapezoid weight for t

    const int chunk = blockIdx.y;
    const int t0    = chunk * T_PER_CHUNK;
    const int tid   = threadIdx.y * NG + threadIdx.x;

    const float tau0 = tau0p[0];
    for (int t = tid; t < T_PER_CHUNK; t += 192) {
        const int tg = t0 + t;
        sh_d[t] = tau0 - tau[tg];
        const float wl = (tg == 0)         ? 0.0f : (tau[tg] - tau[tg - 1]);
        const float wr = (tg == N_TAU - 1) ? 0.0f : (tau[tg + 1] - tau[tg]);
        sh_w[t] = 0.5f * (wl + wr);
    }
    __syncthreads();

    const int   kidx = blockIdx.x * K_PER_BLOCK + threadIdx.y;
    const float kval = kk_arr[kidx];
    const int   g    = threadIdx.x;        // ell group 0..11 -> ells 4g..4g+3

    const float xmin = bx[0];
    const float xmax = bx[N_X - 1];
    const float sc   = (float)(N_X - 1) / (xmax - xmin);

    const float4* __restrict__ P0 = (const float4*)p0t;  // row = NG float4s
    const float4* __restrict__ P1 = (const float4*)p1t;
    const float4* __restrict__ P2 = (const float4*)p2t;
    const float4* __restrict__ PE = (const float4*)pet;

    float aT0 = 0.f, aT1 = 0.f, aT2 = 0.f, aT3 = 0.f;
    float aE0 = 0.f, aE1 = 0.f, aE2 = 0.f, aE3 = 0.f;

    const int sbase = kidx * N_TAU + t0;

    #pragma unroll 2
    for (int t = 0; t < T_PER_CHUNK; ++t) {
        const float x   = kval * sh_d[t];
        float pos = (x - xmin) * sc;
        pos = fminf(fmaxf(pos, 0.0f), (float)(N_X - 1));
        int i0 = (int)pos;
        if (i0 > N_X - 2) i0 = N_X - 2;
        const float w = pos - (float)i0;

        const float wt = sh_w[t];
        const float s0 = S0[sbase + t] * wt;
        const float s1 = S1[sbase + t] * wt;
        const float s2 = S2[sbase + t] * wt;
        const float se = SE[sbase + t] * wt;

        const int r = i0 * NG + g;
        const float4 a0 = P0[r], b0 = P0[r + NG];
        const float4 a1 = P1[r], b1 = P1[r + NG];
        const float4 a2 = P2[r], b2 = P2[r + NG];
        const float4 ae = PE[r], be = PE[r + NG];

        // lerp: f = a + w*(b-a)
        const float f0x = a0.x + w * (b0.x - a0.x);
        const float f0y = a0.y + w * (b0.y - a0.y);
        const float f0z = a0.z + w * (b0.z - a0.z);
        const float f0w = a0.w + w * (b0.w - a0.w);
        const float f1x = a1.x + w * (b1.x - a1.x);
        const float f1y = a1.y + w * (b1.y - a1.y);
        const float f1z = a1.z + w * (b1.z - a1.z);
        const float f1w = a1.w + w * (b1.w - a1.w);
        const float f2x = a2.x + w * (b2.x - a2.x);
        const float f2y = a2.y + w * (b2.y - a2.y);
        const float f2z = a2.z + w * (b2.z - a2.z);
        const float f2w = a2.w + w * (b2.w - a2.w);
        const float fex = ae.x + w * (be.x - ae.x);
        const float fey = ae.y + w * (be.y - ae.y);
        const float fez = ae.z + w * (be.z - ae.z);
        const float few = ae.w + w * (be.w - ae.w);

        aT0 += s0 * f0x + s1 * f1x + s2 * f2x;
        aT1 += s0 * f0y + s1 * f1y + s2 * f2y;
        aT2 += s0 * f0z + s1 * f1z + s2 * f2z;
        aT3 += s0 * f0w + s1 * f1w + s2 * f2w;
        aE0 += se * fex;
        aE1 += se * fey;
        aE2 += se * fez;
        aE3 += se * few;
    }

    const int ell = 4 * g;
    g_Tl[chunk][ell + 0][kidx] = aT0;
    g_Tl[chunk][ell + 1][kidx] = aT1;
    g_Tl[chunk][ell + 2][kidx] = aT2;
    g_Tl[chunk][ell + 3][kidx] = aT3;
    g_El[chunk][ell + 0][kidx] = aE0;
    g_El[chunk][ell + 1][kidx] = aE1;
    g_El[chunk][ell + 2][kidx] = aE2;
    g_El[chunk][ell + 3][kidx] = aE3;
}

// ---------------------------------------------------------------------------
// Kernel 2: k-quadrature -> Cl.  grid: 48 blocks (one per ell), 128 threads.
// ---------------------------------------------------------------------------
__global__ __launch_bounds__(128) void spectrum_k2(
    const float* __restrict__ kk_arr,
    const float* __restrict__ Asp,
    const float* __restrict__ nsp,
    float* __restrict__ out)
{
    const int ell = blockIdx.x;
    const int tid = threadIdx.x;

    const float A_s  = Asp[0];
    const float n_s  = nsp[0];
    const float PI_F = 3.14159265358979323846f;
    const float pref = A_s * 2.0f * PI_F * PI_F;   // k^2 * P_R = pref*(k/kp)^(ns-1)/k

    double tt = 0.0, ee = 0.0, te = 0.0;
    for (int i = tid; i < N_K; i += 128) {
        const float kv = kk_arr[i];
        const float wl = (i == 0)        ? 0.0f : (kv - kk_arr[i - 1]);
        const float wr = (i == N_K - 1)  ? 0.0f : (kk_arr[i + 1] - kv);
        const float wtrap = 0.5f * (wl + wr);
        const float weight = wtrap * pref * powf(kv / 0.05f, n_s - 1.0f) / kv;

        const float T = g_Tl[0][ell][i] + g_Tl[1][ell][i]
                      + g_Tl[2][ell][i] + g_Tl[3][ell][i];
        const float E = g_El[0][ell][i] + g_El[1][ell][i]
                      + g_El[2][ell][i] + g_El[3][ell][i];

        tt += (double)(weight * T * T);
        ee += (double)(weight * E * E);
        te += (double)(weight * T * E);
    }

    __shared__ double sTT[128], sEE[128], sTE[128];
    sTT[tid] = tt; sEE[tid] = ee; sTE[tid] = te;
    __syncthreads();
    for (int s = 64; s > 0; s >>= 1) {
        if (tid < s) {
            sTT[tid] += sTT[tid + s];
            sEE[tid] += sEE[tid + s];
            sTE[tid] += sTE[tid + s];
        }
        __syncthreads();
    }
    if (tid == 0) {
        const double c = 2.0 / 3.14159265358979323846;
        out[0 * N_ELL + ell] = (float)(c * sTT[0]);
        out[1 * N_ELL + ell] = (float)(c * sEE[0]);
        out[2 * N_ELL + ell] = (float)(c * sTE[0]);
    }
}

extern "C" void kernel_launch(void* const* d_in, const int* in_sizes, int n_in,
                              void* d_out, int out_size)
{
    const float* k    = (const float*)d_in[0];
    const float* tau  = (const float*)d_in[1];
    const float* tau0 = (const float*)d_in[2];
    const float* S0   = (const float*)d_in[3];
    const float* S1   = (const float*)d_in[4];
    const float* S2   = (const float*)d_in[5];
    const float* SE   = (const float*)d_in[6];
    const float* bx   = (const float*)d_in[7];
    const float* p0   = (const float*)d_in[8];
    const float* p1   = (const float*)d_in[9];
    const float* p2   = (const float*)d_in[10];
    const float* pe   = (const float*)d_in[11];
    const float* As   = (const float*)d_in[12];
    const float* ns   = (const float*)d_in[13];
    float* out = (float*)d_out;

    dim3 grid1(N_K / K_PER_BLOCK, N_CHUNK);   // (64, 4)
    dim3 block1(NG, K_PER_BLOCK);             // (12, 16) = 192 threads
    spectrum_k1<<<grid1, block1>>>(k, tau, tau0, S0, S1, S2, SE,
                                   bx, p0, p1, p2, pe);

    spectrum_k2<<<N_ELL, 128>>>(k, As, ns, out);
}

// round 2
// speedup vs baseline: 1.8074x; 1.8074x over previous
#include <cuda_runtime.h>
#include <cuda_fp16.h>

#define N_X   20000
#define N_ELL 48
#define N_K   1024
#define N_TAU 600

#define N_CHUNK 8
#define T_PER_CHUNK (N_TAU / N_CHUNK)   // 75
#define K_PER_BLOCK 16
#define NG 12                            // ell groups of 4

// Scratch partial sums: [chunk][ell][k]
__device__ float g_Tl[N_CHUNK][N_ELL][N_K];
__device__ float g_El[N_CHUNK][N_ELL][N_K];

// Packed fp16 tables: per row i0, per group g: 16 halves =
// {p0 e0,e1, p0 e2,e3, p1 e0,e1, p1 e2,e3, p2 e0,e1, p2 e2,e3, pe e0,e1, pe e2,e3}
// row stride = 12 groups * 2 uint4 = 24 uint4 (384 B).
__device__ uint4 g_pack[N_X * 24];

__device__ __forceinline__ unsigned h2u(__half2 h) {
    return *reinterpret_cast<unsigned*>(&h);
}
__device__ __forceinline__ __half2 u2h(unsigned u) {
    __half2 h; *reinterpret_cast<unsigned*>(&h) = u; return h;
}

// ---------------------------------------------------------------------------
// Kernel 0: pack 4 float tables -> interleaved fp16.
// One thread per (i0, g): reads 4 float4s, writes 2 uint4s.
// ---------------------------------------------------------------------------
__global__ __launch_bounds__(256) void pack_tables(
    const float* __restrict__ p0t, const float* __restrict__ p1t,
    const float* __restrict__ p2t, const float* __restrict__ pet)
{
    const int tid = blockIdx.x * 256 + threadIdx.x;   // 0 .. N_X*12-1
    if (tid >= N_X * NG) return;
    const float4* __restrict__ P0 = (const float4*)p0t;
    const float4* __restrict__ P1 = (const float4*)p1t;
    const float4* __restrict__ P2 = (const float4*)p2t;
    const float4* __restrict__ PE = (const float4*)pet;
    const float4 v0 = P0[tid], v1 = P1[tid], v2 = P2[tid], ve = PE[tid];

    uint4 oA, oB;
    oA.x = h2u(__float22half2_rn(make_float2(v0.x, v0.y)));
    oA.y = h2u(__float22half2_rn(make_float2(v0.z, v0.w)));
    oA.z = h2u(__float22half2_rn(make_float2(v1.x, v1.y)));
    oA.w = h2u(__float22half2_rn(make_float2(v1.z, v1.w)));
    oB.x = h2u(__float22half2_rn(make_float2(v2.x, v2.y)));
    oB.y = h2u(__float22half2_rn(make_float2(v2.z, v2.w)));
    oB.z = h2u(__float22half2_rn(make_float2(ve.x, ve.y)));
    oB.w = h2u(__float22half2_rn(make_float2(ve.z, ve.w)));
    g_pack[tid * 2]     = oA;
    g_pack[tid * 2 + 1] = oB;
}

// ---------------------------------------------------------------------------
// Kernel 1: fused interpolation + source product + tau-trapezoid partial sums.
// block: (12, 16) -> 12 ell-groups x 16 k.  grid: (64 k-blocks, 8 tau-chunks)
// ---------------------------------------------------------------------------
__global__ __launch_bounds__(192) void spectrum_k1(
    const float* __restrict__ kk_arr,
    const float* __restrict__ tau,
    const float* __restrict__ tau0p,
    const float* __restrict__ S0,
    const float* __restrict__ S1,
    const float* __restrict__ S2,
    const float* __restrict__ SE,
    const float* __restrict__ bx)
{
    __shared__ float sh_d[T_PER_CHUNK];   // tau0 - tau[t]
    __shared__ float sh_w[T_PER_CHUNK];   // trapezoid weight for t

    const int chunk = blockIdx.y;
    const int t0    = chunk * T_PER_CHUNK;
    const int tid   = threadIdx.y * NG + threadIdx.x;

    const float tau0 = tau0p[0];
    for (int t = tid; t < T_PER_CHUNK; t += 192) {
        const int tg = t0 + t;
        sh_d[t] = tau0 - tau[tg];
        const float wl = (tg == 0)         ? 0.0f : (tau[tg] - tau[tg - 1]);
        const float wr = (tg == N_TAU - 1) ? 0.0f : (tau[tg + 1] - tau[tg]);
        sh_w[t] = 0.5f * (wl + wr);
    }
    __syncthreads();

    const int   kidx = blockIdx.x * K_PER_BLOCK + threadIdx.y;
    const float kval = kk_arr[kidx];
    const int   g    = threadIdx.x;

    const float xmin = bx[0];
    const float xmax = bx[N_X - 1];
    const float sc   = (float)(N_X - 1) / (xmax - xmin);

    float aT0 = 0.f, aT1 = 0.f, aT2 = 0.f, aT3 = 0.f;
    float aE0 = 0.f, aE1 = 0.f, aE2 = 0.f, aE3 = 0.f;

    const int sbase = kidx * N_TAU + t0;
    const uint4* __restrict__ TP = g_pack;

    #pragma unroll 3
    for (int t = 0; t < T_PER_CHUNK; ++t) {
        const float x   = kval * sh_d[t];
        float pos = (x - xmin) * sc;
        pos = fminf(fmaxf(pos, 0.0f), (float)(N_X - 1));
        int i0 = (int)pos;
        if (i0 > N_X - 2) i0 = N_X - 2;
        const float w = pos - (float)i0;

        const float wt = sh_w[t];
        const float s0 = S0[sbase + t] * wt;
        const float s1 = S1[sbase + t] * wt;
        const float s2 = S2[sbase + t] * wt;
        const float se = SE[sbase + t] * wt;

        const int ra = i0 * 24 + g * 2;
        const uint4 A0 = TP[ra],      A1 = TP[ra + 1];
        const uint4 B0 = TP[ra + 24], B1 = TP[ra + 25];

        const __half2 w2 = __float2half2_rn(w);
        // lerp in half2: f = a + w*(b-a)
        const __half2 h0a = __hfma2(w2, __hsub2(u2h(B0.x), u2h(A0.x)), u2h(A0.x));
        const __half2 h0b = __hfma2(w2, __hsub2(u2h(B0.y), u2h(A0.y)), u2h(A0.y));
        const __half2 h1a = __hfma2(w2, __hsub2(u2h(B0.z), u2h(A0.z)), u2h(A0.z));
        const __half2 h1b = __hfma2(w2, __hsub2(u2h(B0.w), u2h(A0.w)), u2h(A0.w));
        const __half2 h2a = __hfma2(w2, __hsub2(u2h(B1.x), u2h(A1.x)), u2h(A1.x));
        const __half2 h2b = __hfma2(w2, __hsub2(u2h(B1.y), u2h(A1.y)), u2h(A1.y));
        const __half2 hea = __hfma2(w2, __hsub2(u2h(B1.z), u2h(A1.z)), u2h(A1.z));
        const __half2 heb = __hfma2(w2, __hsub2(u2h(B1.w), u2h(A1.w)), u2h(A1.w));

        const float2 f0a = __half22float2(h0a);
        const float2 f0b = __half22float2(h0b);
        const float2 f1a = __half22float2(h1a);
        const float2 f1b = __half22float2(h1b);
        const float2 f2a = __half22float2(h2a);
        const float2 f2b = __half22float2(h2b);
        const float2 fea = __half22float2(hea);
        const float2 feb = __half22float2(heb);

        aT0 += s0 * f0a.x + s1 * f1a.x + s2 * f2a.x;
        aT1 += s0 * f0a.y + s1 * f1a.y + s2 * f2a.y;
        aT2 += s0 * f0b.x + s1 * f1b.x + s2 * f2b.x;
        aT3 += s0 * f0b.y + s1 * f1b.y + s2 * f2b.y;
        aE0 += se * fea.x;
        aE1 += se * fea.y;
        aE2 += se * feb.x;
        aE3 += se * feb.y;
    }

    const int ell = 4 * g;
    g_Tl[chunk][ell + 0][kidx] = aT0;
    g_Tl[chunk][ell + 1][kidx] = aT1;
    g_Tl[chunk][ell + 2][kidx] = aT2;
    g_Tl[chunk][ell + 3][kidx] = aT3;
    g_El[chunk][ell + 0][kidx] = aE0;
    g_El[chunk][ell + 1][kidx] = aE1;
    g_El[chunk][ell + 2][kidx] = aE2;
    g_El[chunk][ell + 3][kidx] = aE3;
}

// ---------------------------------------------------------------------------
// Kernel 2: k-quadrature -> Cl.  48 blocks (one per ell), 512 threads.
// ---------------------------------------------------------------------------
__global__ __launch_bounds__(512) void spectrum_k2(
    const float* __restrict__ kk_arr,
    const float* __restrict__ Asp,
    const float* __restrict__ nsp,
    float* __restrict__ out)
{
    const int ell = blockIdx.x;
    const int tid = threadIdx.x;

    const float A_s  = Asp[0];
    const float n_s  = nsp[0];
    const float PI_F = 3.14159265358979323846f;
    const float pref = A_s * 2.0f * PI_F * PI_F;

    double tt = 0.0, ee = 0.0, te = 0.0;
    for (int i = tid; i < N_K; i += 512) {
        const float kv = kk_arr[i];
        const float wl = (i == 0)        ? 0.0f : (kv - kk_arr[i - 1]);
        const float wr = (i == N_K - 1)  ? 0.0f : (kk_arr[i + 1] - kv);
        // (k/kp)^(ns-1) via fast exp2/log2
        const float pw = exp2f((n_s - 1.0f) * log2f(kv * 20.0f));
        const float weight = 0.5f * (wl + wr) * pref * pw / kv;

        float T = 0.f, E = 0.f;
        #pragma unroll
        for (int c = 0; c < N_CHUNK; ++c) {
            T += g_Tl[c][ell][i];
            E += g_El[c][ell][i];
        }
        tt += (double)(weight * T * T);
        ee += (double)(weight * E * E);
        te += (double)(weight * T * E);
    }

    // warp reduction
    #pragma unroll
    for (int o = 16; o > 0; o >>= 1) {
        tt += __shfl_down_sync(0xffffffffu, tt, o);
        ee += __shfl_down_sync(0xffffffffu, ee, o);
        te += __shfl_down_sync(0xffffffffu, te, o);
    }
    __shared__ double sT[16], sE[16], sX[16];
    const int wid = tid >> 5, lid = tid & 31;
    if (lid == 0) { sT[wid] = tt; sE[wid] = ee; sX[wid] = te; }
    __syncthreads();
    if (tid < 16) {
        tt = sT[tid]; ee = sE[tid]; te = sX[tid];
        #pragma unroll
        for (int o = 8; o > 0; o >>= 1) {
            tt += __shfl_down_sync(0xffffu, tt, o, 16);
            ee += __shfl_down_sync(0xffffu, ee, o, 16);
            te += __shfl_down_sync(0xffffu, te, o, 16);
        }
        if (tid == 0) {
            const double c = 2.0 / 3.14159265358979323846;
            out[0 * N_ELL + ell] = (float)(c * tt);
            out[1 * N_ELL + ell] = (float)(c * ee);
            out[2 * N_ELL + ell] = (float)(c * te);
        }
    }
}

extern "C" void kernel_launch(void* const* d_in, const int* in_sizes, int n_in,
                              void* d_out, int out_size)
{
    const float* k    = (const float*)d_in[0];
    const float* tau  = (const float*)d_in[1];
    const float* tau0 = (const float*)d_in[2];
    const float* S0   = (const float*)d_in[3];
    const float* S1   = (const float*)d_in[4];
    const float* S2   = (const float*)d_in[5];
    const float* SE   = (const float*)d_in[6];
    const float* bx   = (const float*)d_in[7];
    const float* p0   = (const float*)d_in[8];
    const float* p1   = (const float*)d_in[9];
    const float* p2   = (const float*)d_in[10];
    const float* pe   = (const float*)d_in[11];
    const float* As   = (const float*)d_in[12];
    const float* ns   = (const float*)d_in[13];
    float* out = (float*)d_out;

    pack_tables<<<(N_X * NG + 255) / 256, 256>>>(p0, p1, p2, pe);

    dim3 grid1(N_K / K_PER_BLOCK, N_CHUNK);   // (64, 8)
    dim3 block1(NG, K_PER_BLOCK);             // (12, 16) = 192 threads
    spectrum_k1<<<grid1, block1>>>(k, tau, tau0, S0, S1, S2, SE, bx);

    spectrum_k2<<<N_ELL, 512>>>(k, As, ns, out);
}